// round 5
// baseline (speedup 1.0000x reference)
#include <cuda_runtime.h>
#include <math.h>

#define D_MODEL 1024
#define LSEQ    2048
#define NTOK    8192          // B * L
#define NHEAD   16
#define HDIM    64
#define FFH     2048

// ---------------- scratch (allocation-free: __device__ globals) ----------------
__device__ float g_h  [NTOK * D_MODEL];       // LN output (reused for both LNs)
__device__ float g_qkv[NTOK * 3 * D_MODEL];   // QKV projection
__device__ float g_ctx[NTOK * D_MODEL];       // attention context
__device__ float g_x1 [NTOK * D_MODEL];       // post-attention residual
__device__ float g_ff [NTOK * FFH];           // FF1 output (post-GELU)

// ---------------- LayerNorm ----------------
__global__ __launch_bounds__(256) void ln_kernel(const float* __restrict__ x,
                                                 const float* __restrict__ g,
                                                 const float* __restrict__ b,
                                                 float* __restrict__ out) {
    int row = blockIdx.x;
    int t = threadIdx.x;                    // 256 threads, 4 floats each
    const float4* xr = (const float4*)(x + (size_t)row * D_MODEL);
    float4 v = xr[t];
    float s  = v.x + v.y + v.z + v.w;
    float ss = v.x*v.x + v.y*v.y + v.z*v.z + v.w*v.w;
    #pragma unroll
    for (int o = 16; o > 0; o >>= 1) {
        s  += __shfl_xor_sync(0xffffffffu, s,  o);
        ss += __shfl_xor_sync(0xffffffffu, ss, o);
    }
    __shared__ float ssum[8], ssq[8];
    __shared__ float stats[2];
    int warp = t >> 5, lane = t & 31;
    if (lane == 0) { ssum[warp] = s; ssq[warp] = ss; }
    __syncthreads();
    if (t == 0) {
        float S = 0.f, SS = 0.f;
        #pragma unroll
        for (int i = 0; i < 8; i++) { S += ssum[i]; SS += ssq[i]; }
        float mu  = S * (1.0f / D_MODEL);
        float var = SS * (1.0f / D_MODEL) - mu * mu;
        stats[0] = mu;
        stats[1] = rsqrtf(var + 1e-5f);
    }
    __syncthreads();
    float mu = stats[0], rstd = stats[1];
    float4 gg = ((const float4*)g)[t];
    float4 bb = ((const float4*)b)[t];
    float4 o;
    o.x = (v.x - mu) * rstd * gg.x + bb.x;
    o.y = (v.y - mu) * rstd * gg.y + bb.y;
    o.z = (v.z - mu) * rstd * gg.z + bb.z;
    o.w = (v.w - mu) * rstd * gg.w + bb.w;
    ((float4*)(out + (size_t)row * D_MODEL))[t] = o;
}

// ---------------- SGEMM: C[M,N] = A[M,K] @ W[K,N] + bias (+gelu|+res) ----------
// BM=BN=128, BK=8, 256 threads, 8x8 microtile.
// EPI: 0 = bias, 1 = bias + exact GELU, 2 = bias + residual
template<int EPI>
__global__ __launch_bounds__(256) void sgemm(int M, int N, int K,
                                             const float* __restrict__ A,
                                             const float* __restrict__ W,
                                             const float* __restrict__ bias,
                                             const float* __restrict__ res,
                                             float* __restrict__ C) {
    __shared__ float As[8][128];
    __shared__ float Bs[8][128];
    int bm = blockIdx.y * 128;
    int bn = blockIdx.x * 128;
    int tid  = threadIdx.x;
    int trow = tid >> 4;          // 0..15
    int tcol = tid & 15;          // 0..15

    int aRow = tid >> 1;          // 0..127
    int aK   = (tid & 1) * 4;     // 0 or 4
    int bRow = tid >> 5;          // 0..7
    int bCol = (tid & 31) * 4;    // 0..124

    const float* Aptr = A + (size_t)(bm + aRow) * K + aK;
    const float* Wptr = W + (size_t)bRow * N + bn + bCol;

    float acc[8][8] = {};

    for (int k0 = 0; k0 < K; k0 += 8) {
        float4 av = *(const float4*)(Aptr + k0);
        float4 bv = *(const float4*)(Wptr + (size_t)k0 * N);
        As[aK + 0][aRow] = av.x;
        As[aK + 1][aRow] = av.y;
        As[aK + 2][aRow] = av.z;
        As[aK + 3][aRow] = av.w;
        *(float4*)&Bs[bRow][bCol] = bv;
        __syncthreads();
        #pragma unroll
        for (int kk = 0; kk < 8; kk++) {
            float ra[8], rb[8];
            *(float4*)(ra)     = *(const float4*)&As[kk][trow * 8];
            *(float4*)(ra + 4) = *(const float4*)&As[kk][trow * 8 + 4];
            *(float4*)(rb)     = *(const float4*)&Bs[kk][tcol * 8];
            *(float4*)(rb + 4) = *(const float4*)&Bs[kk][tcol * 8 + 4];
            #pragma unroll
            for (int i = 0; i < 8; i++)
                #pragma unroll
                for (int j = 0; j < 8; j++)
                    acc[i][j] += ra[i] * rb[j];
        }
        __syncthreads();
    }

    #pragma unroll
    for (int i = 0; i < 8; i++) {
        int row = bm + trow * 8 + i;
        #pragma unroll
        for (int j4 = 0; j4 < 2; j4++) {
            int col = bn + tcol * 8 + j4 * 4;
            float4 bs = *(const float4*)&bias[col];
            float v0 = acc[i][j4 * 4 + 0] + bs.x;
            float v1 = acc[i][j4 * 4 + 1] + bs.y;
            float v2 = acc[i][j4 * 4 + 2] + bs.z;
            float v3 = acc[i][j4 * 4 + 3] + bs.w;
            if (EPI == 1) {  // exact GELU
                v0 = 0.5f * v0 * (1.0f + erff(v0 * 0.70710678118654752f));
                v1 = 0.5f * v1 * (1.0f + erff(v1 * 0.70710678118654752f));
                v2 = 0.5f * v2 * (1.0f + erff(v2 * 0.70710678118654752f));
                v3 = 0.5f * v3 * (1.0f + erff(v3 * 0.70710678118654752f));
            }
            if (EPI == 2) {  // residual
                float4 rv = *(const float4*)&res[(size_t)row * N + col];
                v0 += rv.x; v1 += rv.y; v2 += rv.z; v3 += rv.w;
            }
            *(float4*)&C[(size_t)row * N + col] = make_float4(v0, v1, v2, v3);
        }
    }
}

// ---------------- Flash attention (fp32, Br=Bc=64, Dh=64) ----------------
// grid: (L/64, B*H), block: 256 (16x16 microtile threads)
#define AP 65    // padded pitch for transposed tiles
__global__ __launch_bounds__(256) void attn_kernel(const float* __restrict__ qkv,
                                                   float* __restrict__ ctx) {
    extern __shared__ float sm[];
    float* Qs = sm;                         // [64][AP]  (d-major: Qs[d][i])
    float* Ks = sm + 64 * AP;               // [64][AP]  (d-major: Ks[d][j])
    float* Vs = sm + 2 * 64 * AP;           // [64][64]  (natural: Vs[k][dd])
    float* Ps = sm + 2 * 64 * AP + 64 * 64; // [64][AP]  (k-major: Ps[k][i])

    int tid  = threadIdx.x;
    int trow = tid >> 4;   // 0..15 -> owns rows trow*4..+3
    int tcol = tid & 15;   // 0..15 -> owns cols tcol*4..+3
    int qb = blockIdx.x;
    int bh = blockIdx.y;
    int bb = bh >> 4;
    int h  = bh & 15;

    // load Q tile (64 x 64), transposed into Qs[d][i]
    const float* qbase = qkv + ((size_t)(bb * LSEQ + qb * 64)) * (3 * D_MODEL) + h * HDIM;
    for (int t = tid; t < 1024; t += 256) {
        int row = t >> 4;
        int c4  = (t & 15) << 2;
        float4 v = *(const float4*)(qbase + (size_t)row * (3 * D_MODEL) + c4);
        Qs[(c4 + 0) * AP + row] = v.x;
        Qs[(c4 + 1) * AP + row] = v.y;
        Qs[(c4 + 2) * AP + row] = v.z;
        Qs[(c4 + 3) * AP + row] = v.w;
    }

    float accO[4][4] = {};
    float mrow[4], lrow[4];
    #pragma unroll
    for (int r = 0; r < 4; r++) { mrow[r] = -INFINITY; lrow[r] = 0.f; }

    for (int kb = 0; kb < LSEQ / 64; kb++) {
        __syncthreads();   // protect Ks/Vs/Ps from previous iteration's readers
        const float* kbase = qkv + ((size_t)(bb * LSEQ + kb * 64)) * (3 * D_MODEL)
                             + D_MODEL + h * HDIM;
        const float* vbase = kbase + D_MODEL;
        for (int t = tid; t < 1024; t += 256) {
            int row = t >> 4;
            int c4  = (t & 15) << 2;
            float4 kv = *(const float4*)(kbase + (size_t)row * (3 * D_MODEL) + c4);
            Ks[(c4 + 0) * AP + row] = kv.x;
            Ks[(c4 + 1) * AP + row] = kv.y;
            Ks[(c4 + 2) * AP + row] = kv.z;
            Ks[(c4 + 3) * AP + row] = kv.w;
            float4 vv = *(const float4*)(vbase + (size_t)row * (3 * D_MODEL) + c4);
            *(float4*)&Vs[row * 64 + c4] = vv;
        }
        __syncthreads();

        // S = Q @ K^T  (4x4 microtile, rank-1 over d)
        float accS[4][4] = {};
        #pragma unroll 8
        for (int d = 0; d < 64; d++) {
            float a[4], b[4];
            #pragma unroll
            for (int r = 0; r < 4; r++) a[r] = Qs[d * AP + trow * 4 + r];
            #pragma unroll
            for (int c = 0; c < 4; c++) b[c] = Ks[d * AP + tcol * 4 + c];
            #pragma unroll
            for (int r = 0; r < 4; r++)
                #pragma unroll
                for (int c = 0; c < 4; c++)
                    accS[r][c] += a[r] * b[c];
        }

        // online softmax (row groups of 16 tx-threads live in one half-warp)
        float alpha[4];
        #pragma unroll
        for (int r = 0; r < 4; r++) {
            float rmax = -INFINITY;
            #pragma unroll
            for (int c = 0; c < 4; c++) {
                accS[r][c] *= 0.125f;   // 1/sqrt(64)
                rmax = fmaxf(rmax, accS[r][c]);
            }
            #pragma unroll
            for (int o = 8; o > 0; o >>= 1)
                rmax = fmaxf(rmax, __shfl_xor_sync(0xffffffffu, rmax, o, 16));
            float mnew = fmaxf(mrow[r], rmax);
            alpha[r] = __expf(mrow[r] - mnew);
            float rsum = 0.f;
            #pragma unroll
            for (int c = 0; c < 4; c++) {
                float p = __expf(accS[r][c] - mnew);
                accS[r][c] = p;
                rsum += p;
            }
            #pragma unroll
            for (int o = 8; o > 0; o >>= 1)
                rsum += __shfl_xor_sync(0xffffffffu, rsum, o, 16);
            lrow[r] = lrow[r] * alpha[r] + rsum;
            mrow[r] = mnew;
        }

        // store P transposed: Ps[k][i]
        #pragma unroll
        for (int r = 0; r < 4; r++)
            #pragma unroll
            for (int c = 0; c < 4; c++)
                Ps[(tcol * 4 + c) * AP + trow * 4 + r] = accS[r][c];
        __syncthreads();

        // O = O*alpha + P @ V
        #pragma unroll
        for (int r = 0; r < 4; r++)
            #pragma unroll
            for (int c = 0; c < 4; c++)
                accO[r][c] *= alpha[r];
        #pragma unroll 8
        for (int k = 0; k < 64; k++) {
            float a[4];
            #pragma unroll
            for (int r = 0; r < 4; r++) a[r] = Ps[k * AP + trow * 4 + r];
            float4 bv = *(const float4*)&Vs[k * 64 + tcol * 4];
            float b[4] = {bv.x, bv.y, bv.z, bv.w};
            #pragma unroll
            for (int r = 0; r < 4; r++)
                #pragma unroll
                for (int c = 0; c < 4; c++)
                    accO[r][c] += a[r] * b[c];
        }
    }

    // normalize and write ctx[b, q, h*64 + dd]
    #pragma unroll
    for (int r = 0; r < 4; r++) {
        float inv = 1.0f / lrow[r];
        int orow = bb * LSEQ + qb * 64 + trow * 4 + r;
        float4 o = make_float4(accO[r][0] * inv, accO[r][1] * inv,
                               accO[r][2] * inv, accO[r][3] * inv);
        *(float4*)&ctx[(size_t)orow * D_MODEL + h * HDIM + tcol * 4] = o;
    }
}

#define ATTN_SMEM ((2 * 64 * AP + 64 * 64 + 64 * AP) * 4)

// ---------------- launch ----------------
extern "C" void kernel_launch(void* const* d_in, const int* in_sizes, int n_in,
                              void* d_out, int out_size) {
    (void)in_sizes; (void)n_in; (void)out_size;
    const float* x     = (const float*)d_in[0];
    const float* qkv_w = (const float*)d_in[1];
    const float* qkv_b = (const float*)d_in[2];
    const float* out_w = (const float*)d_in[3];
    const float* out_b = (const float*)d_in[4];
    const float* ff1_w = (const float*)d_in[5];
    const float* ff1_b = (const float*)d_in[6];
    const float* ff2_w = (const float*)d_in[7];
    const float* ff2_b = (const float*)d_in[8];
    const float* ln1_g = (const float*)d_in[9];
    const float* ln1_b = (const float*)d_in[10];
    const float* ln2_g = (const float*)d_in[11];
    const float* ln2_b = (const float*)d_in[12];
    float* out = (float*)d_out;

    float *h, *qkvbuf, *ctx, *x1, *ff;
    cudaGetSymbolAddress((void**)&h,      g_h);
    cudaGetSymbolAddress((void**)&qkvbuf, g_qkv);
    cudaGetSymbolAddress((void**)&ctx,    g_ctx);
    cudaGetSymbolAddress((void**)&x1,     g_x1);
    cudaGetSymbolAddress((void**)&ff,     g_ff);

    cudaFuncSetAttribute(attn_kernel,
                         cudaFuncAttributeMaxDynamicSharedMemorySize, ATTN_SMEM);

    // 1) h = LN1(x)
    ln_kernel<<<NTOK, 256>>>(x, ln1_g, ln1_b, h);
    // 2) qkv = h @ qkv_w + qkv_b      [8192, 3072]
    sgemm<0><<<dim3(3 * D_MODEL / 128, NTOK / 128), 256>>>(
        NTOK, 3 * D_MODEL, D_MODEL, h, qkv_w, qkv_b, nullptr, qkvbuf);
    // 3) ctx = attention(qkv)
    attn_kernel<<<dim3(LSEQ / 64, 4 * NHEAD), 256, ATTN_SMEM>>>(qkvbuf, ctx);
    // 4) x1 = x + ctx @ out_w + out_b
    sgemm<2><<<dim3(D_MODEL / 128, NTOK / 128), 256>>>(
        NTOK, D_MODEL, D_MODEL, ctx, out_w, out_b, x, x1);
    // 5) h = LN2(x1)
    ln_kernel<<<NTOK, 256>>>(x1, ln2_g, ln2_b, h);
    // 6) ff = gelu(h @ ff1_w + ff1_b)  [8192, 2048]
    sgemm<1><<<dim3(FFH / 128, NTOK / 128), 256>>>(
        NTOK, FFH, D_MODEL, h, ff1_w, ff1_b, nullptr, ff);
    // 7) out = x1 + ff @ ff2_w + ff2_b
    sgemm<2><<<dim3(D_MODEL / 128, NTOK / 128), 256>>>(
        NTOK, D_MODEL, FFH, ff, ff2_w, ff2_b, x1, out);
}